// round 1
// baseline (speedup 1.0000x reference)
#include <cuda_runtime.h>
#include <cstdint>

// Problem constants (fixed by setup_inputs)
#define BDIM 4096          // B
#define DDIM 4096          // D
#define N2   8192          // 2B
#define INVT 10.0f         // 1/TEMP

// ---------------------------------------------------------------------------
// Scratch (device globals: no allocation allowed)
// ---------------------------------------------------------------------------
__device__ float g_sim[(size_t)BDIM * N2];   // 128 MB: fused similarity matrix
__device__ float g_diag[BDIM];
__device__ float g_rowloss[BDIM];
__device__ float g_colpart_m[32 * BDIM];
__device__ float g_colpart_s[32 * BDIM];
__device__ float g_colloss[BDIM];

// ---------------------------------------------------------------------------
// Packed f32x2 helpers (FFMA2 is only reachable via PTX fma.rn.f32x2)
// ---------------------------------------------------------------------------
__device__ __forceinline__ unsigned long long pack2(float lo, float hi) {
    unsigned long long r;
    asm("mov.b64 %0, {%1, %2};" : "=l"(r) : "f"(lo), "f"(hi));
    return r;
}
__device__ __forceinline__ void unpack2(unsigned long long v, float& lo, float& hi) {
    asm("mov.b64 {%0, %1}, %2;" : "=f"(lo), "=f"(hi) : "l"(v));
}
__device__ __forceinline__ void fma2(unsigned long long& d,
                                     unsigned long long a,
                                     unsigned long long b) {
    asm("fma.rn.f32x2 %0, %1, %2, %0;" : "+l"(d) : "l"(a), "l"(b));
}

// ---------------------------------------------------------------------------
// Kernel 1: diag[i] = 0.5*sims_local[i,i] + 0.5*dot(im[i,:], s[i,:])
// ---------------------------------------------------------------------------
__global__ void diag_kernel(const float* __restrict__ im,
                            const float* __restrict__ s,
                            const float* __restrict__ sl) {
    int i = blockIdx.x;
    const float* a = im + (size_t)i * DDIM;
    const float* b = s  + (size_t)i * DDIM;
    float sum = 0.f;
    for (int k = threadIdx.x; k < DDIM; k += 256) sum += a[k] * b[k];
    __shared__ float red[256];
    red[threadIdx.x] = sum;
    __syncthreads();
    for (int off = 128; off > 0; off >>= 1) {
        if (threadIdx.x < off) red[threadIdx.x] += red[threadIdx.x + off];
        __syncthreads();
    }
    if (threadIdx.x == 0)
        g_diag[i] = 0.5f * sl[(size_t)i * N2 + i] + 0.5f * red[0];
}

// ---------------------------------------------------------------------------
// Kernel 2: GEMM  g_sim[i,j] = 0.5*sl[i,j] + 0.5 * dot(im[i,:], s[j,:])
// Tiles: 128(M) x 128(N) x 16(K), 256 threads, per-thread 4x16 microtile,
// accumulators packed pairwise along N (FFMA2).
// ---------------------------------------------------------------------------
#define BMT 128
#define BNT 128
#define BKT 16

__global__ __launch_bounds__(256)
void gemm_kernel(const float* __restrict__ A,   // im  [BDIM, DDIM]
                 const float* __restrict__ Bm,  // s   [N2,   DDIM]
                 const float* __restrict__ SL,  // sims_local [BDIM, N2]
                 float* __restrict__ C) {       // g_sim
    __shared__ float As[BKT][BMT];
    __shared__ float Bs[BKT][BNT];

    const int tid = threadIdx.x;
    const int bx  = blockIdx.x;        // N tile (0..63)
    const int by  = blockIdx.y;        // M tile (0..31)
    const int tx  = tid & 7;           // N sub (0..7), 16 cols each
    const int ty  = tid >> 3;          // M sub (0..31), 4 rows each
    const int tn0 = tx * 16;
    const int tm0 = ty * 4;

    const int lr = tid >> 2;           // 0..63 loader row
    const int lq = (tid & 3) * 4;      // loader float4 col within BK

    const float* AgA = A  + ((size_t)(by * BMT + lr))      * DDIM + lq;
    const float* AgB = A  + ((size_t)(by * BMT + lr + 64)) * DDIM + lq;
    const float* BgA = Bm + ((size_t)(bx * BNT + lr))      * DDIM + lq;
    const float* BgB = Bm + ((size_t)(bx * BNT + lr + 64)) * DDIM + lq;

    unsigned long long acc[4][8];
    #pragma unroll
    for (int m = 0; m < 4; m++)
        #pragma unroll
        for (int n = 0; n < 8; n++) acc[m][n] = 0ull;

    for (int kt = 0; kt < DDIM; kt += BKT) {
        float4 av0 = *(const float4*)(AgA + kt);
        float4 av1 = *(const float4*)(AgB + kt);
        float4 bv0 = *(const float4*)(BgA + kt);
        float4 bv1 = *(const float4*)(BgB + kt);
        __syncthreads();   // previous iteration's smem reads complete
        As[lq + 0][lr]      = av0.x; As[lq + 1][lr]      = av0.y;
        As[lq + 2][lr]      = av0.z; As[lq + 3][lr]      = av0.w;
        As[lq + 0][lr + 64] = av1.x; As[lq + 1][lr + 64] = av1.y;
        As[lq + 2][lr + 64] = av1.z; As[lq + 3][lr + 64] = av1.w;
        Bs[lq + 0][lr]      = bv0.x; Bs[lq + 1][lr]      = bv0.y;
        Bs[lq + 2][lr]      = bv0.z; Bs[lq + 3][lr]      = bv0.w;
        Bs[lq + 0][lr + 64] = bv1.x; Bs[lq + 1][lr + 64] = bv1.y;
        Bs[lq + 2][lr + 64] = bv1.z; Bs[lq + 3][lr + 64] = bv1.w;
        __syncthreads();

        #pragma unroll
        for (int k = 0; k < BKT; k++) {
            float4 af  = *(const float4*)&As[k][tm0];
            float4 bf0 = *(const float4*)&Bs[k][tn0];
            float4 bf1 = *(const float4*)&Bs[k][tn0 + 4];
            float4 bf2 = *(const float4*)&Bs[k][tn0 + 8];
            float4 bf3 = *(const float4*)&Bs[k][tn0 + 12];
            unsigned long long bp[8];
            bp[0] = pack2(bf0.x, bf0.y); bp[1] = pack2(bf0.z, bf0.w);
            bp[2] = pack2(bf1.x, bf1.y); bp[3] = pack2(bf1.z, bf1.w);
            bp[4] = pack2(bf2.x, bf2.y); bp[5] = pack2(bf2.z, bf2.w);
            bp[6] = pack2(bf3.x, bf3.y); bp[7] = pack2(bf3.z, bf3.w);
            float am[4] = {af.x, af.y, af.z, af.w};
            #pragma unroll
            for (int m = 0; m < 4; m++) {
                unsigned long long ap = pack2(am[m], am[m]);
                #pragma unroll
                for (int n = 0; n < 8; n++) fma2(acc[m][n], ap, bp[n]);
            }
        }
    }

    // Epilogue: C = 0.5*SL + 0.5*acc, float4 stores
    #pragma unroll
    for (int m = 0; m < 4; m++) {
        size_t row  = (size_t)(by * BMT + tm0 + m);
        size_t base = row * N2 + (size_t)(bx * BNT + tn0);
        #pragma unroll
        for (int q = 0; q < 4; q++) {
            float4 sl4 = *(const float4*)(SL + base + q * 4);
            float x0, x1, x2, x3;
            unpack2(acc[m][2 * q],     x0, x1);
            unpack2(acc[m][2 * q + 1], x2, x3);
            float4 o;
            o.x = 0.5f * sl4.x + 0.5f * x0;
            o.y = 0.5f * sl4.y + 0.5f * x1;
            o.z = 0.5f * sl4.z + 0.5f * x2;
            o.w = 0.5f * sl4.w + 0.5f * x3;
            *(float4*)(C + base + q * 4) = o;
        }
    }
}

// ---------------------------------------------------------------------------
// Online-lse combine helper semantics: (m, s) with lse = m + log(s)
// ---------------------------------------------------------------------------

// Kernel 3: per-row logsumexp over all 2B columns with conditional masking of
// the second half (val > diag -> 0, and the 0 STILL participates in the lse).
__global__ void row_lse_kernel() {
    int i = blockIdx.x;
    float d = g_diag[i];
    const float* row = g_sim + (size_t)i * N2;
    float m = -1e30f, s = 0.f;
    for (int j = threadIdx.x; j < N2; j += 256) {
        float v = row[j];
        if (j >= BDIM && v > d) v = 0.f;
        float x = v * INVT;
        if (x > m)            { s = s * __expf(m - x) + 1.f; m = x; }
        else if (x > m - 15.f){ s += __expf(x - m); }
        // else: contribution < 3e-7, negligible (saves the MUFU)
    }
    __shared__ float sm[256], ss[256];
    sm[threadIdx.x] = m; ss[threadIdx.x] = s;
    __syncthreads();
    for (int off = 128; off > 0; off >>= 1) {
        if (threadIdx.x < off) {
            float m1 = sm[threadIdx.x],       s1 = ss[threadIdx.x];
            float m2 = sm[threadIdx.x + off], s2 = ss[threadIdx.x + off];
            float M = fmaxf(m1, m2);
            ss[threadIdx.x] = s1 * __expf(m1 - M) + s2 * __expf(m2 - M);
            sm[threadIdx.x] = M;
        }
        __syncthreads();
    }
    if (threadIdx.x == 0)
        g_rowloss[i] = sm[0] + __logf(ss[0]) - d * INVT;
}

// Kernel 4: column-lse partials over the FIRST block (unmasked), 128-row chunks
__global__ void col_part_kernel() {
    int j  = blockIdx.x * 128 + threadIdx.x;   // column 0..4095
    int r0 = blockIdx.y * 128;
    float m = -1e30f, s = 0.f;
    for (int r = r0; r < r0 + 128; r++) {
        float x = g_sim[(size_t)r * N2 + j] * INVT;
        if (x > m)            { s = s * __expf(m - x) + 1.f; m = x; }
        else if (x > m - 15.f){ s += __expf(x - m); }
    }
    g_colpart_m[blockIdx.y * BDIM + j] = m;
    g_colpart_s[blockIdx.y * BDIM + j] = s;
}

// Kernel 5: combine 32 column partials (fixed order -> deterministic)
__global__ void col_final_kernel() {
    int j = blockIdx.x * 128 + threadIdx.x;
    float m = -1e30f, s = 0.f;
    for (int c = 0; c < 32; c++) {
        float m2 = g_colpart_m[c * BDIM + j];
        float s2 = g_colpart_s[c * BDIM + j];
        float M = fmaxf(m, m2);
        s = s * __expf(m - M) + s2 * __expf(m2 - M);
        m = M;
    }
    g_colloss[j] = m + __logf(s) - g_diag[j] * INVT;
}

// Kernel 6: deterministic final sum -> scalar loss
__global__ void final_kernel(float* __restrict__ out) {
    int t = threadIdx.x;  // 1024 threads
    float sum = 0.f;
    for (int i = t; i < BDIM; i += 1024)
        sum += g_rowloss[i] + g_colloss[i];
    __shared__ float red[1024];
    red[t] = sum;
    __syncthreads();
    for (int off = 512; off > 0; off >>= 1) {
        if (t < off) red[t] += red[t + off];
        __syncthreads();
    }
    if (t == 0) out[0] = red[0] * (1.0f / (float)BDIM);
}

// ---------------------------------------------------------------------------
extern "C" void kernel_launch(void* const* d_in, const int* in_sizes, int n_in,
                              void* d_out, int out_size) {
    const float* im = (const float*)d_in[0];   // [4096, 4096]
    const float* s  = (const float*)d_in[1];   // [8192, 4096]
    const float* sl = (const float*)d_in[2];   // [4096, 8192]
    float* out = (float*)d_out;

    diag_kernel<<<BDIM, 256>>>(im, s, sl);

    float* simp = nullptr;
    cudaGetSymbolAddress((void**)&simp, g_sim);
    dim3 gg(N2 / BNT, BDIM / BMT);             // (64, 32)
    gemm_kernel<<<gg, 256>>>(im, s, sl, simp);

    row_lse_kernel<<<BDIM, 256>>>();
    col_part_kernel<<<dim3(32, 32), 128>>>();
    col_final_kernel<<<32, 128>>>();
    final_kernel<<<1, 1024>>>(out);
}

// round 3
// speedup vs baseline: 14.3934x; 14.3934x over previous
#include <cuda_runtime.h>
#include <cuda_bf16.h>
#include <cstdint>

// Problem constants
#define BDIM 4096
#define DDIM 4096
#define N2   8192
#define INVT 10.0f

// ---------------------------------------------------------------------------
// Scratch (device globals; no allocation allowed)
// ---------------------------------------------------------------------------
__device__ float          g_sim[(size_t)BDIM * N2];     // 128 MB
__device__ __nv_bfloat16  g_imb[(size_t)BDIM * DDIM];   // 32 MB
__device__ __nv_bfloat16  g_sb[(size_t)N2 * DDIM];      // 64 MB
__device__ float g_diag[BDIM];
__device__ float g_rowloss[BDIM];
__device__ float g_colpart_m[32 * BDIM];
__device__ float g_colpart_s[32 * BDIM];
__device__ float g_colloss[BDIM];

// ---------------------------------------------------------------------------
// PTX helpers (all non-arch-specific: sm_80/sm_90 baseline features)
// ---------------------------------------------------------------------------
__device__ __forceinline__ uint32_t smem_u32(const void* p) {
    uint32_t a;
    asm("{ .reg .u64 t; cvta.to.shared.u64 t, %1; cvt.u32.u64 %0, t; }"
        : "=r"(a) : "l"(p));
    return a;
}

__device__ __forceinline__ void cpasync16(uint32_t dst, const void* src) {
    asm volatile("cp.async.cg.shared.global [%0], [%1], 16;"
                 :: "r"(dst), "l"(src) : "memory");
}
#define CP_COMMIT() asm volatile("cp.async.commit_group;" ::: "memory")
#define CP_WAIT2()  asm volatile("cp.async.wait_group 2;" ::: "memory")

__device__ __forceinline__ void ldsm4(uint32_t* r, uint32_t addr) {
    asm volatile("ldmatrix.sync.aligned.m8n8.x4.shared.b16 {%0,%1,%2,%3}, [%4];"
                 : "=r"(r[0]), "=r"(r[1]), "=r"(r[2]), "=r"(r[3]) : "r"(addr));
}

__device__ __forceinline__ void mma16816(float* d, const uint32_t* a,
                                         const uint32_t* b) {
    asm volatile(
        "mma.sync.aligned.m16n8k16.row.col.f32.bf16.bf16.f32 "
        "{%0,%1,%2,%3}, {%4,%5,%6,%7}, {%8,%9}, {%0,%1,%2,%3};"
        : "+f"(d[0]), "+f"(d[1]), "+f"(d[2]), "+f"(d[3])
        : "r"(a[0]), "r"(a[1]), "r"(a[2]), "r"(a[3]), "r"(b[0]), "r"(b[1]));
}

// ---------------------------------------------------------------------------
// fp32 -> bf16 conversion
// ---------------------------------------------------------------------------
__global__ void cvt_kernel(const float* __restrict__ src,
                           __nv_bfloat16* __restrict__ dst, int n4) {
    int i = blockIdx.x * blockDim.x + threadIdx.x;
    int stride = gridDim.x * blockDim.x;
    for (; i < n4; i += stride) {
        float4 f = ((const float4*)src)[i];
        __nv_bfloat162 lo = __floats2bfloat162_rn(f.x, f.y);
        __nv_bfloat162 hi = __floats2bfloat162_rn(f.z, f.w);
        uint2 u;
        u.x = *reinterpret_cast<uint32_t*>(&lo);
        u.y = *reinterpret_cast<uint32_t*>(&hi);
        ((uint2*)dst)[i] = u;
    }
}

// ---------------------------------------------------------------------------
// diag[i] = 0.5*sl[i,i] + 0.5*dot(im[i,:], s[i,:])   (fp32 exact)
// ---------------------------------------------------------------------------
__global__ void diag_kernel(const float* __restrict__ im,
                            const float* __restrict__ s,
                            const float* __restrict__ sl) {
    int i = blockIdx.x;
    const float4* a = (const float4*)(im + (size_t)i * DDIM);
    const float4* b = (const float4*)(s  + (size_t)i * DDIM);
    float sum = 0.f;
    for (int k = threadIdx.x; k < DDIM / 4; k += 256) {
        float4 av = a[k], bv = b[k];
        sum += av.x * bv.x + av.y * bv.y + av.z * bv.z + av.w * bv.w;
    }
    __shared__ float red[256];
    red[threadIdx.x] = sum;
    __syncthreads();
    for (int off = 128; off > 0; off >>= 1) {
        if (threadIdx.x < off) red[threadIdx.x] += red[threadIdx.x + off];
        __syncthreads();
    }
    if (threadIdx.x == 0)
        g_diag[i] = 0.5f * sl[(size_t)i * N2 + i] + 0.5f * red[0];
}

// ---------------------------------------------------------------------------
// bf16 mma.sync GEMM:  C[4096,8192] = 0.5*SL + 0.5 * (imb @ sb^T)
// CTA 128x256, K-chunk 32, 4 cp.async stages, 256 threads (8 warps, 2x4).
// ---------------------------------------------------------------------------
#define BM 128
#define BN 256
#define BK 32
#define RS 40                       // halves per padded smem row (80 B)
#define STAGES 4
#define A_HALVES (BM * RS)          // 5120
#define B_HALVES (BN * RS)          // 10240
#define STG_HALVES (A_HALVES + B_HALVES)
#define SMEM_GEMM (STAGES * STG_HALVES * 2)   // 122880 B
#define NKIT (DDIM / BK)            // 128

__global__ __launch_bounds__(256, 1)
void gemm_mma(const __nv_bfloat16* __restrict__ A,   // [4096][4096]
              const __nv_bfloat16* __restrict__ B,   // [8192][4096]
              const float* __restrict__ SL,
              float* __restrict__ C) {
    extern __shared__ __align__(1024) __nv_bfloat16 sm[];
    const uint32_t sbase = smem_u32(sm);
    const int tid   = threadIdx.x;
    const int lane  = tid & 31;
    const int wid   = tid >> 5;
    const int warpM = wid >> 2;     // 0..1
    const int warpN = wid & 3;      // 0..3
    const int m0 = blockIdx.y * BM;
    const int n0 = blockIdx.x * BN;

    // Loader assignment (16B chunks): A has 512 chunks, B has 1024.
    const int lrowA0 = tid >> 2;          // for cid = tid (+64/row-group per +256)
    const int lcol   = (tid & 3) * 8;     // halves

    float acc[4][8][4];
    #pragma unroll
    for (int mf = 0; mf < 4; mf++)
        #pragma unroll
        for (int nf = 0; nf < 8; nf++)
            #pragma unroll
            for (int q = 0; q < 4; q++) acc[mf][nf][q] = 0.f;

    // Prologue: stages 0..2
    #pragma unroll
    for (int st = 0; st < STAGES - 1; st++) {
        const int k0 = st * BK;
        uint32_t sA = sbase + st * STG_HALVES * 2;
        uint32_t sB = sA + A_HALVES * 2;
        #pragma unroll
        for (int i = 0; i < 2; i++) {
            int row = lrowA0 + i * 64;
            cpasync16(sA + (row * RS + lcol) * 2,
                      A + (size_t)(m0 + row) * DDIM + k0 + lcol);
        }
        #pragma unroll
        for (int i = 0; i < 4; i++) {
            int row = lrowA0 + i * 64;
            cpasync16(sB + (row * RS + lcol) * 2,
                      B + (size_t)(n0 + row) * DDIM + k0 + lcol);
        }
        CP_COMMIT();
    }

    for (int it = 0; it < NKIT; it++) {
        CP_WAIT2();
        __syncthreads();

        // Prefetch stage it+3 (empty commit group in the tail keeps the
        // wait_group count constant).
        if (it + 3 < NKIT) {
            const int st = (it + 3) & 3;
            const int k0 = (it + 3) * BK;
            uint32_t sA = sbase + st * STG_HALVES * 2;
            uint32_t sB = sA + A_HALVES * 2;
            #pragma unroll
            for (int i = 0; i < 2; i++) {
                int row = lrowA0 + i * 64;
                cpasync16(sA + (row * RS + lcol) * 2,
                          A + (size_t)(m0 + row) * DDIM + k0 + lcol);
            }
            #pragma unroll
            for (int i = 0; i < 4; i++) {
                int row = lrowA0 + i * 64;
                cpasync16(sB + (row * RS + lcol) * 2,
                          B + (size_t)(n0 + row) * DDIM + k0 + lcol);
            }
        }
        CP_COMMIT();

        // Compute on stage it&3
        uint32_t sA = sbase + (it & 3) * STG_HALVES * 2;
        uint32_t sB = sA + A_HALVES * 2;
        #pragma unroll
        for (int s = 0; s < 2; s++) {       // two k16 steps in BK=32
            uint32_t a[4][4], b[4][4];
            #pragma unroll
            for (int mf = 0; mf < 4; mf++) {
                int row = warpM * 64 + mf * 16 + (lane & 15);
                int ko  = s * 16 + (lane >> 4) * 8;
                ldsm4(a[mf], sA + (row * RS + ko) * 2);
            }
            const int q = lane >> 3;
            #pragma unroll
            for (int nf2 = 0; nf2 < 4; nf2++) {
                int row = warpN * 64 + nf2 * 16 + (q >> 1) * 8 + (lane & 7);
                int ko  = s * 16 + (q & 1) * 8;
                ldsm4(b[nf2], sB + (row * RS + ko) * 2);
            }
            #pragma unroll
            for (int mf = 0; mf < 4; mf++)
                #pragma unroll
                for (int nf = 0; nf < 8; nf++)
                    mma16816(acc[mf][nf], a[mf], b[nf >> 1] + (nf & 1) * 2);
        }
    }

    // Epilogue: C = 0.5*SL + 0.5*acc (float2 per c-frag pair)
    #pragma unroll
    for (int mf = 0; mf < 4; mf++) {
        #pragma unroll
        for (int h = 0; h < 2; h++) {
            int rowg = m0 + warpM * 64 + mf * 16 + (lane >> 2) + h * 8;
            size_t rbase = (size_t)rowg * N2 + n0 + warpN * 64 + (lane & 3) * 2;
            #pragma unroll
            for (int nf = 0; nf < 8; nf++) {
                size_t off = rbase + nf * 8;
                float2 sl2 = *(const float2*)(SL + off);
                float2 o;
                o.x = 0.5f * sl2.x + 0.5f * acc[mf][nf][h * 2 + 0];
                o.y = 0.5f * sl2.y + 0.5f * acc[mf][nf][h * 2 + 1];
                *(float2*)(C + off) = o;
            }
        }
    }
}

// ---------------------------------------------------------------------------
// Row logsumexp with conditional second-half masking
// ---------------------------------------------------------------------------
__global__ void row_lse_kernel() {
    int i = blockIdx.x;
    float d = g_diag[i];
    const float* row = g_sim + (size_t)i * N2;
    float m = -1e30f, s = 0.f;
    for (int j = threadIdx.x; j < N2; j += 256) {
        float v = row[j];
        if (j >= BDIM && v > d) v = 0.f;
        float x = v * INVT;
        if (x > m)             { s = s * __expf(m - x) + 1.f; m = x; }
        else if (x > m - 15.f) { s += __expf(x - m); }
    }
    __shared__ float sm[256], ss[256];
    sm[threadIdx.x] = m; ss[threadIdx.x] = s;
    __syncthreads();
    for (int off = 128; off > 0; off >>= 1) {
        if (threadIdx.x < off) {
            float m1 = sm[threadIdx.x],       s1 = ss[threadIdx.x];
            float m2 = sm[threadIdx.x + off], s2 = ss[threadIdx.x + off];
            float M = fmaxf(m1, m2);
            ss[threadIdx.x] = s1 * __expf(m1 - M) + s2 * __expf(m2 - M);
            sm[threadIdx.x] = M;
        }
        __syncthreads();
    }
    if (threadIdx.x == 0)
        g_rowloss[i] = sm[0] + __logf(ss[0]) - d * INVT;
}

// Column-lse partials over first block (128-row chunks)
__global__ void col_part_kernel() {
    int j  = blockIdx.x * 128 + threadIdx.x;
    int r0 = blockIdx.y * 128;
    float m = -1e30f, s = 0.f;
    for (int r = r0; r < r0 + 128; r++) {
        float x = g_sim[(size_t)r * N2 + j] * INVT;
        if (x > m)             { s = s * __expf(m - x) + 1.f; m = x; }
        else if (x > m - 15.f) { s += __expf(x - m); }
    }
    g_colpart_m[blockIdx.y * BDIM + j] = m;
    g_colpart_s[blockIdx.y * BDIM + j] = s;
}

__global__ void col_final_kernel() {
    int j = blockIdx.x * 128 + threadIdx.x;
    float m = -1e30f, s = 0.f;
    for (int c = 0; c < 32; c++) {
        float m2 = g_colpart_m[c * BDIM + j];
        float s2 = g_colpart_s[c * BDIM + j];
        float M = fmaxf(m, m2);
        s = s * __expf(m - M) + s2 * __expf(m2 - M);
        m = M;
    }
    g_colloss[j] = m + __logf(s) - g_diag[j] * INVT;
}

__global__ void final_kernel(float* __restrict__ out) {
    int t = threadIdx.x;
    float sum = 0.f;
    for (int i = t; i < BDIM; i += 1024)
        sum += g_rowloss[i] + g_colloss[i];
    __shared__ float red[1024];
    red[t] = sum;
    __syncthreads();
    for (int off = 512; off > 0; off >>= 1) {
        if (t < off) red[t] += red[t + off];
        __syncthreads();
    }
    if (t == 0) out[0] = red[0] * (1.0f / (float)BDIM);
}

// ---------------------------------------------------------------------------
extern "C" void kernel_launch(void* const* d_in, const int* in_sizes, int n_in,
                              void* d_out, int out_size) {
    const float* im = (const float*)d_in[0];   // [4096, 4096]
    const float* s  = (const float*)d_in[1];   // [8192, 4096]
    const float* sl = (const float*)d_in[2];   // [4096, 8192]
    float* out = (float*)d_out;

    __nv_bfloat16 *imb = nullptr, *sbm = nullptr;
    float* simp = nullptr;
    cudaGetSymbolAddress((void**)&imb,  g_imb);
    cudaGetSymbolAddress((void**)&sbm,  g_sb);
    cudaGetSymbolAddress((void**)&simp, g_sim);

    cvt_kernel<<<4096, 256>>>(im, imb, (BDIM * DDIM) / 4);
    cvt_kernel<<<8192, 256>>>(s,  sbm, (N2 * DDIM) / 4);
    diag_kernel<<<BDIM, 256>>>(im, s, sl);

    static bool smem_set = false;
    cudaFuncSetAttribute(gemm_mma, cudaFuncAttributeMaxDynamicSharedMemorySize,
                         SMEM_GEMM);
    (void)smem_set;

    dim3 gg(N2 / BN, BDIM / BM);   // (32, 32)
    gemm_mma<<<gg, 256, SMEM_GEMM>>>(imb, sbm, sl, simp);

    row_lse_kernel<<<BDIM, 256>>>();
    col_part_kernel<<<dim3(32, 32), 128>>>();
    col_final_kernel<<<32, 128>>>();
    final_kernel<<<1, 1024>>>(out);
}